// round 17
// baseline (speedup 1.0000x reference)
#include <cuda_runtime.h>
#include <cuda_fp16.h>
#include <cstdint>

// NTN: out[n,k] = relu( cos(x1@W1[k], x2@W2[k]) + [x1,x2]@V[k] + b[k] )
// R17: R15 main (smem W via cp.async, validated) but x1t staged in REGISTERS
// (32 regs) instead of smem -> removes ~14% of L1 wavefronts + 32KB smem.
// prep_x / prep_w / prep_p2h (tensor-core part2) unchanged from R15.

#define NN 32768
#define DD 128
#define KK 32
#define EPSN 1e-8f

// ---------------- global scratch ----------------
__device__ uint4 gXfrag[2][2048][8][32];   // [mat][rowtile16][ds][lane] fp16 A-frags
__device__ uint4 gWh[32][2][2048];         // [k][chunk][granule] fp16 W
__device__ float gP2[(size_t)NN * KK];     // part2 + bias

// ---------------- helpers ----------------
static __device__ __forceinline__ uint32_t s2u(const void* p) {
    uint32_t a;
    asm("{ .reg .u64 t; cvta.to.shared.u64 t, %1; cvt.u32.u64 %0, t; }"
        : "=r"(a) : "l"(p));
    return a;
}
static __device__ __forceinline__ uint32_t packh2(float a, float b) {
    __half2 h = __floats2half2_rn(a, b);
    return *reinterpret_cast<uint32_t*>(&h);
}

#define LDSM4T(R, addr)                                                         \
    asm volatile("ldmatrix.sync.aligned.m8n8.x4.trans.shared.b16 {%0,%1,%2,%3},[%4];" \
                 : "=r"((R)[0]), "=r"((R)[1]), "=r"((R)[2]), "=r"((R)[3])       \
                 : "r"(addr))

#define HMMA(C, A, B0, B1)                                                      \
    asm volatile("mma.sync.aligned.m16n8k16.row.col.f32.f16.f16.f32 "           \
                 "{%0,%1,%2,%3},{%4,%5,%6,%7},{%8,%9},{%0,%1,%2,%3};"           \
                 : "+f"((C)[0]), "+f"((C)[1]), "+f"((C)[2]), "+f"((C)[3])       \
                 : "r"((A).x), "r"((A).y), "r"((A).z), "r"((A).w),              \
                   "r"(B0), "r"(B1))

static __device__ __forceinline__ void cp16(uint32_t dst, const void* src) {
    asm volatile("cp.async.cg.shared.global [%0], [%1], 16;"
                 :: "r"(dst), "l"(src) : "memory");
}
static __device__ __forceinline__ void cp_commit() {
    asm volatile("cp.async.commit_group;" ::: "memory");
}
template <int N>
static __device__ __forceinline__ void cp_wait() {
    asm volatile("cp.async.wait_group %0;" :: "n"(N) : "memory");
}

// ---------------- prep: X -> fp16 A-fragments ----------------
__global__ __launch_bounds__(256) void prep_x(const float* __restrict__ x1,
                                              const float* __restrict__ x2) {
    int wid  = (blockIdx.x * 256 + threadIdx.x) >> 5;   // 0..4095
    int lane = threadIdx.x & 31;
    int m  = wid >> 11;
    int rt = wid & 2047;
    const float* x = m ? x2 : x1;
    const float* p0 = x + (size_t)(rt * 16 + (lane >> 2)) * DD;
    const float* p1 = p0 + 8 * DD;
    const int c0 = (lane & 3) * 2;
    #pragma unroll
    for (int ds = 0; ds < 8; ds++) {
        int c = ds * 16 + c0;
        float2 v0 = *(const float2*)(p0 + c);
        float2 v1 = *(const float2*)(p1 + c);
        float2 v2 = *(const float2*)(p0 + c + 8);
        float2 v3 = *(const float2*)(p1 + c + 8);
        gXfrag[m][rt][ds][lane] = make_uint4(packh2(v0.x, v0.y), packh2(v1.x, v1.y),
                                             packh2(v2.x, v2.y), packh2(v3.x, v3.y));
    }
}

// ---------------- prep: W -> fp16 granules ----------------
// t bits: e8:0-2, d:3-9, mat:10, ch:11, k:12-16
__global__ __launch_bounds__(256) void prep_w(const float* __restrict__ W1,
                                              const float* __restrict__ W2) {
    int t   = blockIdx.x * 256 + threadIdx.x;   // 0..131071
    int e8  = t & 7;
    int d   = (t >> 3) & 127;
    int mat = (t >> 10) & 1;
    int ch  = (t >> 11) & 1;
    int k   = t >> 12;
    const float* w = (mat ? W2 : W1) + (size_t)k * DD * DD + (size_t)d * DD
                   + ch * 64 + e8 * 8;
    uint32_t hh[4];
    #pragma unroll
    for (int j = 0; j < 4; j++) hh[j] = packh2(w[2 * j], w[2 * j + 1]);
    gWh[k][ch][mat * 1024 + d * 8 + e8] = make_uint4(hh[0], hh[1], hh[2], hh[3]);
}

// ---------------- prep: part2 + bias via tensor cores ----------------
#define VROWB 80
__global__ __launch_bounds__(256) void prep_p2h(const float* __restrict__ Vg,
                                                const float* __restrict__ bg) {
    __shared__ __align__(16) char vsm[256 * VROWB];
    __shared__ float bs[KK];
    const int tid  = threadIdx.x;
    const int lane = tid & 31;
    const int w    = tid >> 5;
    {
        const int d = tid;
        __half* row = (__half*)(vsm + d * VROWB);
        #pragma unroll 8
        for (int kc = 0; kc < KK; kc++)
            row[kc] = __float2half_rn(Vg[kc * 256 + d]);
    }
    if (tid < KK) bs[tid] = bg[tid];
    __syncthreads();

    const uint32_t sbv = s2u(vsm);
    const int arow  = (lane & 7) + ((lane >> 3) & 1) * 8;
    const int half8 = lane >> 4;
    const uint32_t boff = (uint32_t)(arow * VROWB + half8 * 16);
    const int rtb = blockIdx.x * 16 + w * 2;

    float cc[2][4][4];
    #pragma unroll
    for (int mt = 0; mt < 2; mt++)
        #pragma unroll
        for (int nt = 0; nt < 4; nt++)
            #pragma unroll
            for (int q = 0; q < 4; q++) cc[mt][nt][q] = 0.f;

    #pragma unroll
    for (int ds = 0; ds < 16; ds++) {
        const int m  = ds >> 3;
        const int dl = ds & 7;
        uint4 a0 = gXfrag[m][rtb][dl][lane];
        uint4 a1 = gXfrag[m][rtb + 1][dl][lane];
        uint32_t bb[2][4];
        const uint32_t tb = sbv + (uint32_t)(ds * 16 * VROWB) + boff;
        LDSM4T(bb[0], tb);
        LDSM4T(bb[1], tb + 32);
        #pragma unroll
        for (int cb = 0; cb < 2; cb++) {
            HMMA(cc[0][cb * 2],     a0, bb[cb][0], bb[cb][1]);
            HMMA(cc[1][cb * 2],     a1, bb[cb][0], bb[cb][1]);
            HMMA(cc[0][cb * 2 + 1], a0, bb[cb][2], bb[cb][3]);
            HMMA(cc[1][cb * 2 + 1], a1, bb[cb][2], bb[cb][3]);
        }
    }

    const int rb = blockIdx.x * 256 + w * 32;
    #pragma unroll
    for (int mt = 0; mt < 2; mt++)
        #pragma unroll
        for (int nt = 0; nt < 4; nt++) {
            const int col  = nt * 8 + 2 * (lane & 3);
            const int row0 = rb + mt * 16 + (lane >> 2);
            float2 v0 = make_float2(cc[mt][nt][0] + bs[col], cc[mt][nt][1] + bs[col + 1]);
            float2 v1 = make_float2(cc[mt][nt][2] + bs[col], cc[mt][nt][3] + bs[col + 1]);
            *(float2*)&gP2[(size_t)row0 * KK + col]       = v0;
            *(float2*)&gP2[(size_t)(row0 + 8) * KK + col] = v1;
        }
}

// ---------------- main kernel ----------------
#define WROWB 144                    // 128B data (64 fp16 cols) + 16B pad
#define WPL   (128 * WROWB)          // 18432 per mat tile
#define CHUNKB (2 * WPL)             // 36864 per chunk (2 mats)
#define SMEM_MAIN (2 * CHUNKB)       // 73728 (both chunks resident; no staging)

__global__ __launch_bounds__(256, 2)
void ntn_main(float* __restrict__ out) {
    extern __shared__ char smem[];
    const uint32_t sb = s2u(smem);
    const int tid  = threadIdx.x;
    const int lane = tid & 31;
    const int w    = tid >> 5;     // warp 0..7: rows 32*w .. +31 (of 256)
    const int k     = blockIdx.y;
    const int rbase = blockIdx.x * 256;
    const int rtb   = blockIdx.x * 16 + w * 2;

    // ---- cp.async BOTH chunks upfront (disjoint buffers) ----
    #pragma unroll
    for (int ch = 0; ch < 2; ch++) {
        #pragma unroll
        for (int i = 0; i < 8; i++) {
            int idx = tid + 256 * i;            // 0..2047
            int mp  = idx >> 10;
            int d   = (idx >> 3) & 127;
            int e8  = idx & 7;
            cp16(sb + ch * CHUNKB + mp * WPL + d * WROWB + e8 * 16,
                 &gWh[k][ch][idx]);
        }
        cp_commit();
    }

    const int arow  = (lane & 7) + ((lane >> 3) & 1) * 8;
    const int half8 = lane >> 4;
    const uint32_t boff = (uint32_t)(arow * WROWB + half8 * 16);

    // ---- A register double-buffer: prefetch step (g=0, ds=0) ----
    uint4 a[2][2];
    a[0][0] = gXfrag[0][rtb][0][lane];
    a[0][1] = gXfrag[0][rtb + 1][0][lane];

    float dv[4]  = {0.f, 0.f, 0.f, 0.f};
    float n1v[4] = {0.f, 0.f, 0.f, 0.f};
    float n2v[4] = {0.f, 0.f, 0.f, 0.f};

    uint2 x1s[16];   // x1t tile staged as packed fp16 in REGISTERS

    cp_wait<1>();
    __syncthreads();

    #pragma unroll 1
    for (int c = 0; c < 2; c++) {
        if (c == 1) { cp_wait<0>(); __syncthreads(); }
        const uint32_t cbuf = sb + c * CHUNKB;

        #pragma unroll 1
        for (int g = 0; g < 2; g++) {
            float cc[2][8][4];
            #pragma unroll
            for (int mt = 0; mt < 2; mt++)
                #pragma unroll
                for (int nt = 0; nt < 8; nt++)
                    #pragma unroll
                    for (int q = 0; q < 4; q++) cc[mt][nt][q] = 0.f;

            #pragma unroll
            for (int ds = 0; ds < 8; ds++) {
                const int cur = ds & 1, nxt = cur ^ 1;
                const int gn = (ds < 7) ? g : (g ^ 1);
                const int dn = (ds < 7) ? (ds + 1) : 0;
                a[nxt][0] = gXfrag[gn][rtb][dn][lane];
                a[nxt][1] = gXfrag[gn][rtb + 1][dn][lane];

                uint32_t bb[4][4];
                const uint32_t tb = cbuf + g * WPL + (uint32_t)(ds * 16 * WROWB) + boff;
                LDSM4T(bb[0], tb);
                LDSM4T(bb[1], tb + 32);
                LDSM4T(bb[2], tb + 64);
                LDSM4T(bb[3], tb + 96);

                #pragma unroll
                for (int cb = 0; cb < 4; cb++) {
                    HMMA(cc[0][cb * 2],     a[cur][0], bb[cb][0], bb[cb][1]);
                    HMMA(cc[1][cb * 2],     a[cur][1], bb[cb][0], bb[cb][1]);
                    HMMA(cc[0][cb * 2 + 1], a[cur][0], bb[cb][2], bb[cb][3]);
                    HMMA(cc[1][cb * 2 + 1], a[cur][1], bb[cb][2], bb[cb][3]);
                }
            }

            if (g == 0) {
                // stage x1t tile as packed fp16 in registers
                #pragma unroll
                for (int mt = 0; mt < 2; mt++)
                    #pragma unroll
                    for (int nt = 0; nt < 8; nt++) {
                        x1s[mt * 8 + nt].x = packh2(cc[mt][nt][0], cc[mt][nt][1]);
                        x1s[mt * 8 + nt].y = packh2(cc[mt][nt][2], cc[mt][nt][3]);
                    }
            } else {
                // fold: x1t (register-staged fp16) against x2t (cc)
                #pragma unroll
                for (int mt = 0; mt < 2; mt++)
                    #pragma unroll
                    for (int nt = 0; nt < 8; nt++) {
                        uint2 pv = x1s[mt * 8 + nt];
                        float2 f0 = __half22float2(*reinterpret_cast<__half2*>(&pv.x));
                        float2 f1 = __half22float2(*reinterpret_cast<__half2*>(&pv.y));
                        const int s0 = mt * 2;
                        float b0 = cc[mt][nt][0], b1 = cc[mt][nt][1];
                        float b2 = cc[mt][nt][2], b3 = cc[mt][nt][3];
                        dv[s0]      = fmaf(f0.x, b0, fmaf(f0.y, b1, dv[s0]));
                        n1v[s0]     = fmaf(f0.x, f0.x, fmaf(f0.y, f0.y, n1v[s0]));
                        n2v[s0]     = fmaf(b0, b0, fmaf(b1, b1, n2v[s0]));
                        dv[s0 + 1]  = fmaf(f1.x, b2, fmaf(f1.y, b3, dv[s0 + 1]));
                        n1v[s0 + 1] = fmaf(f1.x, f1.x, fmaf(f1.y, f1.y, n1v[s0 + 1]));
                        n2v[s0 + 1] = fmaf(b2, b2, fmaf(b3, b3, n2v[s0 + 1]));
                    }
            }
        }
    }

    // ---- lane reduce (4 lanes share a row); rows are warp-exclusive ----
    #pragma unroll
    for (int s = 0; s < 4; s++) {
        #pragma unroll
        for (int off = 1; off <= 2; off <<= 1) {
            dv[s]  += __shfl_xor_sync(0xffffffffu, dv[s],  off);
            n1v[s] += __shfl_xor_sync(0xffffffffu, n1v[s], off);
            n2v[s] += __shfl_xor_sync(0xffffffffu, n2v[s], off);
        }
    }
    if ((lane & 3) == 0) {
        #pragma unroll
        for (int s = 0; s < 4; s++) {
            const int row = w * 32 + (s >> 1) * 16 + (s & 1) * 8 + (lane >> 2);
            float s1 = fmaxf(sqrtf(n1v[s]), EPSN);
            float s2 = fmaxf(sqrtf(n2v[s]), EPSN);
            float v  = dv[s] / (s1 * s2) + gP2[(size_t)(rbase + row) * KK + k];
            out[(size_t)(rbase + row) * KK + k] = fmaxf(v, 0.f);
        }
    }
}

extern "C" void kernel_launch(void* const* d_in, const int* in_sizes, int n_in,
                              void* d_out, int out_size) {
    const float* x1 = (const float*)d_in[0];
    const float* x2 = (const float*)d_in[1];
    const float* W1 = (const float*)d_in[2];
    const float* W2 = (const float*)d_in[3];
    const float* V  = (const float*)d_in[4];
    const float* b  = (const float*)d_in[5];
    float* out = (float*)d_out;

    prep_x<<<512, 256>>>(x1, x2);
    prep_w<<<512, 256>>>(W1, W2);
    prep_p2h<<<NN / 256, 256>>>(V, b);   // reads gXfrag: must follow prep_x

    cudaFuncSetAttribute(ntn_main,
                         cudaFuncAttributeMaxDynamicSharedMemorySize, SMEM_MAIN);
    dim3 grid(NN / 256, KK);
    ntn_main<<<grid, 256, SMEM_MAIN>>>(out);
}